// round 3
// baseline (speedup 1.0000x reference)
#include <cuda_runtime.h>
#include <math.h>

// Problem dims
#define BB 2
#define SS 2048
#define DD 1024
#define HH 16
#define DKK 64
#define DFF 4096
#define NROW 4096   // B*S

// ---------------- scratch (device globals; no allocation allowed) ----------------
__device__ float g_xn [NROW * DD];
__device__ float g_q  [NROW * DD];
__device__ float g_k  [NROW * DD];
__device__ float g_v  [NROW * DD];
__device__ float g_ctx[NROW * DD];
__device__ float g_x1 [NROW * DD];
__device__ float g_h  [NROW * DFF];

// ---------------- LayerNorm (unbiased std, eps added to std) ----------------
__global__ __launch_bounds__(256)
void ln_kernel(const float* __restrict__ x, const float* __restrict__ alpha,
               const float* __restrict__ beta, float* __restrict__ y) {
    __shared__ float red[8];
    int row = blockIdx.x;
    int tid = threadIdx.x;
    const float* xr = x + (size_t)row * DD;
    float4 v = *(const float4*)(xr + tid * 4);
    float s = v.x + v.y + v.z + v.w;
    #pragma unroll
    for (int off = 16; off > 0; off >>= 1) s += __shfl_xor_sync(0xffffffffu, s, off);
    if ((tid & 31) == 0) red[tid >> 5] = s;
    __syncthreads();
    float tot = red[0] + red[1] + red[2] + red[3] + red[4] + red[5] + red[6] + red[7];
    float mean = tot * (1.0f / 1024.0f);
    float dx = v.x - mean, dy = v.y - mean, dz = v.z - mean, dw = v.w - mean;
    float sq = dx * dx + dy * dy + dz * dz + dw * dw;
    #pragma unroll
    for (int off = 16; off > 0; off >>= 1) sq += __shfl_xor_sync(0xffffffffu, sq, off);
    __syncthreads();
    if ((tid & 31) == 0) red[tid >> 5] = sq;
    __syncthreads();
    float var = (red[0] + red[1] + red[2] + red[3] + red[4] + red[5] + red[6] + red[7])
                * (1.0f / 1023.0f);            // ddof=1 (unbiased, torch default)
    float sc = alpha[0] / (sqrtf(var) + 1e-6f); // eps added to std, not var
    float be = beta[0];
    float4 o = make_float4(dx * sc + be, dy * sc + be, dz * sc + be, dw * sc + be);
    *(float4*)(y + (size_t)row * DD + tid * 4) = o;
}

// ---------------- SGEMM 128x128x16, double-buffered, 256 thr, 8x8/thread ----------------
// EPI: 0 = bias + scatter to [B,H,S,DK]; 1 = bias + residual add; 2 = bias + ReLU
template <int EPI>
__global__ __launch_bounds__(256, 2)
void gemm128(const float* __restrict__ A, const float* __restrict__ Bm,
             const float* __restrict__ bias, const float* __restrict__ res,
             float* __restrict__ C, int M, int N, int K) {
    __shared__ float As[2][16][128];
    __shared__ float Bs[2][16][128];
    int tid = threadIdx.x;
    int brow = blockIdx.y * 128;
    int bcol = blockIdx.x * 128;

    int ar[2], ac[2], br[2], bc[2];
    #pragma unroll
    for (int i = 0; i < 2; i++) {
        int f = tid + i * 256;
        ar[i] = f >> 2;  ac[i] = (f & 3) << 2;    // A tile: 128 rows x 16 cols
        br[i] = f >> 5;  bc[i] = (f & 31) << 2;   // B tile: 16 rows x 128 cols
    }
    const float* Abase = A + (size_t)brow * K;
    const float* Bbase = Bm + bcol;

    float4 aReg[2], bReg[2];
    #pragma unroll
    for (int i = 0; i < 2; i++) {
        aReg[i] = *(const float4*)(Abase + (size_t)ar[i] * K + ac[i]);
        bReg[i] = *(const float4*)(Bbase + (size_t)br[i] * N + bc[i]);
    }
    #pragma unroll
    for (int i = 0; i < 2; i++) {
        As[0][ac[i] + 0][ar[i]] = aReg[i].x;
        As[0][ac[i] + 1][ar[i]] = aReg[i].y;
        As[0][ac[i] + 2][ar[i]] = aReg[i].z;
        As[0][ac[i] + 3][ar[i]] = aReg[i].w;
        *(float4*)&Bs[0][br[i]][bc[i]] = bReg[i];
    }
    __syncthreads();

    float acc[8][8];
    #pragma unroll
    for (int i = 0; i < 8; i++)
        #pragma unroll
        for (int j = 0; j < 8; j++) acc[i][j] = 0.0f;

    int tRow = (tid >> 4) << 3;
    int tCol = (tid & 15) << 3;
    int ntiles = K >> 4;

    for (int kt = 0; kt < ntiles; kt++) {
        int cur = kt & 1;
        if (kt + 1 < ntiles) {
            #pragma unroll
            for (int i = 0; i < 2; i++) {
                aReg[i] = *(const float4*)(Abase + (size_t)ar[i] * K + (kt + 1) * 16 + ac[i]);
                bReg[i] = *(const float4*)(Bbase + ((size_t)(kt + 1) * 16 + br[i]) * N + bc[i]);
            }
        }
        #pragma unroll
        for (int kk = 0; kk < 16; kk++) {
            float4 a0 = *(const float4*)&As[cur][kk][tRow];
            float4 a1 = *(const float4*)&As[cur][kk][tRow + 4];
            float4 b0 = *(const float4*)&Bs[cur][kk][tCol];
            float4 b1 = *(const float4*)&Bs[cur][kk][tCol + 4];
            float a[8] = {a0.x, a0.y, a0.z, a0.w, a1.x, a1.y, a1.z, a1.w};
            float b[8] = {b0.x, b0.y, b0.z, b0.w, b1.x, b1.y, b1.z, b1.w};
            #pragma unroll
            for (int i = 0; i < 8; i++)
                #pragma unroll
                for (int j = 0; j < 8; j++)
                    acc[i][j] = fmaf(a[i], b[j], acc[i][j]);
        }
        if (kt + 1 < ntiles) {
            int nb = cur ^ 1;
            #pragma unroll
            for (int i = 0; i < 2; i++) {
                As[nb][ac[i] + 0][ar[i]] = aReg[i].x;
                As[nb][ac[i] + 1][ar[i]] = aReg[i].y;
                As[nb][ac[i] + 2][ar[i]] = aReg[i].z;
                As[nb][ac[i] + 3][ar[i]] = aReg[i].w;
                *(float4*)&Bs[nb][br[i]][bc[i]] = bReg[i];
            }
        }
        __syncthreads();
    }

    // epilogue
    #pragma unroll
    for (int i = 0; i < 8; i++) {
        int row = brow + tRow + i;
        #pragma unroll
        for (int jj = 0; jj < 8; jj += 4) {
            int col = bcol + tCol + jj;
            float4 bv = *(const float4*)(bias + col);
            float4 r;
            r.x = acc[i][jj + 0] + bv.x;
            r.y = acc[i][jj + 1] + bv.y;
            r.z = acc[i][jj + 2] + bv.z;
            r.w = acc[i][jj + 3] + bv.w;
            if (EPI == 1) {
                float4 rv = *(const float4*)(res + (size_t)row * N + col);
                r.x += rv.x; r.y += rv.y; r.z += rv.z; r.w += rv.w;
            }
            if (EPI == 2) {
                r.x = fmaxf(r.x, 0.0f); r.y = fmaxf(r.y, 0.0f);
                r.z = fmaxf(r.z, 0.0f); r.w = fmaxf(r.w, 0.0f);
            }
            if (EPI == 0) {
                // scatter: (row = b*S+s, col = h*DK+dk) -> [((b*H+h)*S+s)*DK+dk]
                int b_ = row >> 11, s_ = row & 2047;
                int h_ = col >> 6,  dkc = col & 63;
                *(float4*)(C + ((((size_t)b_ * HH + h_) * SS + s_) << 6) + dkc) = r;
            } else {
                *(float4*)(C + (size_t)row * N + col) = r;
            }
        }
    }
}

// ---------------- Flash attention, fp32, 64-row q tiles ----------------
// grid (S/64, B*H), 256 threads (16x16 logical), 48KB static smem
__global__ __launch_bounds__(256)
void attn_kernel(const float* __restrict__ q, const float* __restrict__ k,
                 const float* __restrict__ v, const int* __restrict__ mask,
                 float* __restrict__ ctx) {
    __shared__ float Qs[64 * 64];   // Q[r][dk]
    __shared__ float KVs[64 * 64];  // K phase: KT[dk][kv]; V phase: V[kv][dk]
    __shared__ float Ps[64 * 64];   // P[r][kv]

    int tid = threadIdx.x;
    int bh = blockIdx.y;
    int qt = blockIdx.x;
    int b = bh >> 4;
    const float* qbase = q + ((size_t)bh * SS + qt * 64) * DKK;
    const float* kbase = k + (size_t)bh * SS * DKK;
    const float* vbase = v + (size_t)bh * SS * DKK;

    // load Q scaled by 1/sqrt(DK)
    #pragma unroll
    for (int i = 0; i < 4; i++) {
        int f = tid + i * 256;
        int r = f >> 4;
        int c = (f & 15) << 2;
        float4 t = *(const float4*)(qbase + r * 64 + c);
        t.x *= 0.125f; t.y *= 0.125f; t.z *= 0.125f; t.w *= 0.125f;
        *(float4*)(Qs + r * 64 + c) = t;
    }
    int ty = tid >> 4, tx = tid & 15;
    int ty4 = ty << 2, tx4 = tx << 2;

    float o[4][4];
    float mI[4], lI[4];
    #pragma unroll
    for (int i = 0; i < 4; i++) {
        mI[i] = -1e30f; lI[i] = 0.0f;
        #pragma unroll
        for (int j = 0; j < 4; j++) o[i][j] = 0.0f;
    }

    for (int kt = 0; kt < SS / 64; kt++) {
        __syncthreads();  // previous PV done before KVs overwrite (also covers Q load)
        // load K tile transposed: KT[dk][kv]
        #pragma unroll
        for (int i = 0; i < 4; i++) {
            int f = tid + i * 256;
            int r = f >> 4;              // kv within tile
            int c = (f & 15) << 2;       // dk
            float4 t = *(const float4*)(kbase + (size_t)(kt * 64 + r) * 64 + c);
            KVs[(c + 0) * 64 + r] = t.x;
            KVs[(c + 1) * 64 + r] = t.y;
            KVs[(c + 2) * 64 + r] = t.z;
            KVs[(c + 3) * 64 + r] = t.w;
        }
        __syncthreads();

        float s[4][4];
        #pragma unroll
        for (int i = 0; i < 4; i++)
            #pragma unroll
            for (int j = 0; j < 4; j++) s[i][j] = 0.0f;

        #pragma unroll 4
        for (int dk0 = 0; dk0 < 64; dk0 += 4) {
            float4 qv[4], kv4[4];
            #pragma unroll
            for (int i = 0; i < 4; i++) qv[i] = *(const float4*)(Qs + (ty4 + i) * 64 + dk0);
            #pragma unroll
            for (int u = 0; u < 4; u++) kv4[u] = *(const float4*)(KVs + (dk0 + u) * 64 + tx4);
            #pragma unroll
            for (int i = 0; i < 4; i++) {
                float qx = qv[i].x, qy = qv[i].y, qz = qv[i].z, qw = qv[i].w;
                s[i][0] += qx * kv4[0].x + qy * kv4[1].x + qz * kv4[2].x + qw * kv4[3].x;
                s[i][1] += qx * kv4[0].y + qy * kv4[1].y + qz * kv4[2].y + qw * kv4[3].y;
                s[i][2] += qx * kv4[0].z + qy * kv4[1].z + qz * kv4[2].z + qw * kv4[3].z;
                s[i][3] += qx * kv4[0].w + qy * kv4[1].w + qz * kv4[2].w + qw * kv4[3].w;
            }
        }

        // mask (src_mask[b,0,0,t]); scores = -1e9 where mask==0
        int4 mv = *(const int4*)(mask + b * SS + kt * 64 + tx4);
        if (mv.x == 0) { s[0][0] = s[1][0] = s[2][0] = s[3][0] = -1e9f; }
        if (mv.y == 0) { s[0][1] = s[1][1] = s[2][1] = s[3][1] = -1e9f; }
        if (mv.z == 0) { s[0][2] = s[1][2] = s[2][2] = s[3][2] = -1e9f; }
        if (mv.w == 0) { s[0][3] = s[1][3] = s[2][3] = s[3][3] = -1e9f; }

        // online softmax update
        #pragma unroll
        for (int i = 0; i < 4; i++) {
            float rm = fmaxf(fmaxf(s[i][0], s[i][1]), fmaxf(s[i][2], s[i][3]));
            #pragma unroll
            for (int off = 1; off < 16; off <<= 1)
                rm = fmaxf(rm, __shfl_xor_sync(0xffffffffu, rm, off));
            float nm = fmaxf(mI[i], rm);
            float corr = __expf(mI[i] - nm);
            float rs = 0.0f;
            #pragma unroll
            for (int j = 0; j < 4; j++) { s[i][j] = __expf(s[i][j] - nm); rs += s[i][j]; }
            #pragma unroll
            for (int off = 1; off < 16; off <<= 1)
                rs += __shfl_xor_sync(0xffffffffu, rs, off);
            lI[i] = lI[i] * corr + rs;
            mI[i] = nm;
            #pragma unroll
            for (int j = 0; j < 4; j++) o[i][j] *= corr;
            *(float4*)(Ps + (ty4 + i) * 64 + tx4) = make_float4(s[i][0], s[i][1], s[i][2], s[i][3]);
        }
        __syncthreads();  // P written, K phase done

        // load V tile: V[kv][dk]
        #pragma unroll
        for (int i = 0; i < 4; i++) {
            int f = tid + i * 256;
            int r = f >> 4;
            int c = (f & 15) << 2;
            *(float4*)(KVs + r * 64 + c) =
                *(const float4*)(vbase + (size_t)(kt * 64 + r) * 64 + c);
        }
        __syncthreads();

        // O += P @ V
        #pragma unroll 4
        for (int kk = 0; kk < 64; kk += 4) {
            float4 pv[4], vv[4];
            #pragma unroll
            for (int i = 0; i < 4; i++) pv[i] = *(const float4*)(Ps + (ty4 + i) * 64 + kk);
            #pragma unroll
            for (int u = 0; u < 4; u++) vv[u] = *(const float4*)(KVs + (kk + u) * 64 + tx4);
            #pragma unroll
            for (int i = 0; i < 4; i++) {
                float px = pv[i].x, py = pv[i].y, pz = pv[i].z, pw = pv[i].w;
                o[i][0] += px * vv[0].x + py * vv[1].x + pz * vv[2].x + pw * vv[3].x;
                o[i][1] += px * vv[0].y + py * vv[1].y + pz * vv[2].y + pw * vv[3].y;
                o[i][2] += px * vv[0].z + py * vv[1].z + pz * vv[2].z + pw * vv[3].z;
                o[i][3] += px * vv[0].w + py * vv[1].w + pz * vv[2].w + pw * vv[3].w;
            }
        }
    }

    // epilogue: divide by l, write ctx[B,S,D] at (b, s, h*64+dk)
    int h = bh & 15;
    #pragma unroll
    for (int i = 0; i < 4; i++) {
        float inv = 1.0f / lI[i];
        int srow = qt * 64 + ty4 + i;
        float4 r4 = make_float4(o[i][0] * inv, o[i][1] * inv, o[i][2] * inv, o[i][3] * inv);
        *(float4*)(ctx + ((size_t)(b * SS + srow)) * DD + h * 64 + tx4) = r4;
    }
}

// ---------------- launch ----------------
extern "C" void kernel_launch(void* const* d_in, const int* in_sizes, int n_in,
                              void* d_out, int out_size) {
    const float* x    = (const float*)d_in[0];
    const int*   mask = (const int*)  d_in[1];
    const float* Wq   = (const float*)d_in[2];
    const float* bq   = (const float*)d_in[3];
    const float* Wk   = (const float*)d_in[4];
    const float* bk   = (const float*)d_in[5];
    const float* Wv   = (const float*)d_in[6];
    const float* bv   = (const float*)d_in[7];
    const float* Wo   = (const float*)d_in[8];
    const float* bo   = (const float*)d_in[9];
    const float* W1   = (const float*)d_in[10];
    const float* b1   = (const float*)d_in[11];
    const float* W2   = (const float*)d_in[12];
    const float* b2   = (const float*)d_in[13];
    const float* a1   = (const float*)d_in[14];
    const float* be1  = (const float*)d_in[15];
    const float* a2   = (const float*)d_in[16];
    const float* be2  = (const float*)d_in[17];
    float* out = (float*)d_out;

    // Host-side symbol-address queries (no stream work; capture-safe).
    float *xn = nullptr, *q = nullptr, *k = nullptr, *v = nullptr;
    float *ctx = nullptr, *x1 = nullptr, *h = nullptr;
    cudaGetSymbolAddress((void**)&xn,  g_xn);
    cudaGetSymbolAddress((void**)&q,   g_q);
    cudaGetSymbolAddress((void**)&k,   g_k);
    cudaGetSymbolAddress((void**)&v,   g_v);
    cudaGetSymbolAddress((void**)&ctx, g_ctx);
    cudaGetSymbolAddress((void**)&x1,  g_x1);
    cudaGetSymbolAddress((void**)&h,   g_h);

    dim3 blk(256);
    dim3 g_dxd(DD / 128, NROW / 128);   // (8, 32)  for N=1024 outputs
    dim3 g_ffn1(DFF / 128, NROW / 128); // (32, 32) for N=4096 output

    // 1. LN1
    ln_kernel<<<NROW, blk>>>(x, a1, be1, xn);
    // 2-4. QKV projections (scatter epilogue into [B,H,S,DK])
    gemm128<0><<<g_dxd, blk>>>(xn, Wq, bq, nullptr, q, NROW, DD, DD);
    gemm128<0><<<g_dxd, blk>>>(xn, Wk, bk, nullptr, k, NROW, DD, DD);
    gemm128<0><<<g_dxd, blk>>>(xn, Wv, bv, nullptr, v, NROW, DD, DD);
    // 5. attention
    attn_kernel<<<dim3(SS / 64, BB * HH), blk>>>(q, k, v, mask, ctx);
    // 6. O-projection + residual
    gemm128<1><<<g_dxd, blk>>>(ctx, Wo, bo, x, x1, NROW, DD, DD);
    // 7. LN2
    ln_kernel<<<NROW, blk>>>(x1, a2, be2, xn);
    // 8. FFN1 + ReLU
    gemm128<2><<<g_ffn1, blk>>>(xn, W1, b1, nullptr, h, NROW, DFF, DD);
    // 9. FFN2 + residual -> out
    gemm128<1><<<g_dxd, blk>>>(h, W2, b2, x1, out, NROW, DD, DFF);
}

// round 6
// speedup vs baseline: 1.7452x; 1.7452x over previous
#include <cuda_runtime.h>
#include <math.h>
#include <stdint.h>

// Problem dims
#define BB 2
#define SS 2048
#define DD 1024
#define HH 16
#define DKK 64
#define DFF 4096
#define NROW 4096   // B*S

// ---------------- scratch (device globals; no allocation allowed) ----------------
__device__ float g_xn [NROW * DD];
__device__ float g_q  [NROW * DD];
__device__ float g_k  [NROW * DD];
__device__ float g_v  [NROW * DD];
__device__ float g_ctx[NROW * DD];
__device__ float g_x1 [NROW * DD];
__device__ float g_h  [NROW * DFF];

// ---------------- LayerNorm (unbiased std, eps added to std) ----------------
__global__ __launch_bounds__(256)
void ln_kernel(const float* __restrict__ x, const float* __restrict__ alpha,
               const float* __restrict__ beta, float* __restrict__ y) {
    __shared__ float red[8];
    int row = blockIdx.x;
    int tid = threadIdx.x;
    const float* xr = x + (size_t)row * DD;
    float4 v = *(const float4*)(xr + tid * 4);
    float s = v.x + v.y + v.z + v.w;
    #pragma unroll
    for (int off = 16; off > 0; off >>= 1) s += __shfl_xor_sync(0xffffffffu, s, off);
    if ((tid & 31) == 0) red[tid >> 5] = s;
    __syncthreads();
    float tot = red[0] + red[1] + red[2] + red[3] + red[4] + red[5] + red[6] + red[7];
    float mean = tot * (1.0f / 1024.0f);
    float dx = v.x - mean, dy = v.y - mean, dz = v.z - mean, dw = v.w - mean;
    float sq = dx * dx + dy * dy + dz * dz + dw * dw;
    #pragma unroll
    for (int off = 16; off > 0; off >>= 1) sq += __shfl_xor_sync(0xffffffffu, sq, off);
    __syncthreads();
    if ((tid & 31) == 0) red[tid >> 5] = sq;
    __syncthreads();
    float var = (red[0] + red[1] + red[2] + red[3] + red[4] + red[5] + red[6] + red[7])
                * (1.0f / 1023.0f);            // ddof=1 (unbiased, torch default)
    float sc = alpha[0] / (sqrtf(var) + 1e-6f); // eps added to std, not var
    float be = beta[0];
    float4 o = make_float4(dx * sc + be, dy * sc + be, dz * sc + be, dw * sc + be);
    *(float4*)(y + (size_t)row * DD + tid * 4) = o;
}

// ---------------- TF32 tensor-core GEMM, 128x128 tile, kt=32 ----------------
// EPI: 0 = bias + scatter to [B,H,S,DK]; 1 = bias + residual add; 2 = bias + ReLU
#define AS_STRIDE 36    // 128 rows x (32+4)  -> frag-load bank = 4*(lane>>2)+(lane&3), conflict-free
#define BS_STRIDE 136   // 32 rows x (128+8)  -> frag-load bank = 8*(lane&3)+(lane>>2), conflict-free

__device__ __forceinline__ uint32_t f2tf(float f) {
    uint32_t u;
    asm("cvt.rna.tf32.f32 %0, %1;" : "=r"(u) : "f"(f));
    return u;
}

#define MMA_TF32(d, a, b) \
    asm volatile("mma.sync.aligned.m16n8k8.row.col.f32.tf32.tf32.f32 " \
                 "{%0,%1,%2,%3},{%4,%5,%6,%7},{%8,%9},{%0,%1,%2,%3};" \
                 : "+f"(d[0]), "+f"(d[1]), "+f"(d[2]), "+f"(d[3]) \
                 : "r"(a[0]), "r"(a[1]), "r"(a[2]), "r"(a[3]), "r"(b[0]), "r"(b[1]))

template <int EPI>
__global__ __launch_bounds__(256)
void gemm_tc(const float* __restrict__ A, const float* __restrict__ Bm,
             const float* __restrict__ bias, const float* __restrict__ res,
             float* __restrict__ C, int M, int N, int K) {
    __shared__ uint32_t As[128 * AS_STRIDE];  // [m][k], tf32 bits
    __shared__ uint32_t Bs[32 * BS_STRIDE];   // [k][n], tf32 bits

    int tid  = threadIdx.x;
    int lane = tid & 31;
    int wid  = tid >> 5;
    int brow = blockIdx.y * 128;
    int bcol = blockIdx.x * 128;

    int wm = (wid >> 2) * 64;   // warp m base: 0 / 64
    int wn = (wid & 3) * 32;    // warp n base: 0/32/64/96
    int gr = lane >> 2;         // 0..7
    int gk = lane & 3;          // 0..3

    // global-load thread mapping (coalesced)
    int am[4], ac[4], bk[4], bn[4];
    #pragma unroll
    for (int i = 0; i < 4; i++) {
        int idx = tid + i * 256;
        am[i] = idx >> 3;  ac[i] = (idx & 7) << 2;    // A tile 128x32
        bk[i] = idx >> 5;  bn[i] = (idx & 31) << 2;   // B tile 32x128
    }
    const float* Abase = A + (size_t)brow * K;
    const float* Bbase = Bm + bcol;

    float4 pa[4], pb[4];
    // prefetch tile 0
    #pragma unroll
    for (int i = 0; i < 4; i++) {
        pa[i] = *(const float4*)(Abase + (size_t)am[i] * K + ac[i]);
        pb[i] = *(const float4*)(Bbase + (size_t)bk[i] * N + bn[i]);
    }
    #pragma unroll
    for (int i = 0; i < 4; i++) {
        uint4 ua = make_uint4(f2tf(pa[i].x), f2tf(pa[i].y), f2tf(pa[i].z), f2tf(pa[i].w));
        uint4 ub = make_uint4(f2tf(pb[i].x), f2tf(pb[i].y), f2tf(pb[i].z), f2tf(pb[i].w));
        *(uint4*)&As[am[i] * AS_STRIDE + ac[i]] = ua;
        *(uint4*)&Bs[bk[i] * BS_STRIDE + bn[i]] = ub;
    }
    __syncthreads();

    float acc[4][4][4];
    #pragma unroll
    for (int mt = 0; mt < 4; mt++)
        #pragma unroll
        for (int nt = 0; nt < 4; nt++)
            #pragma unroll
            for (int r = 0; r < 4; r++) acc[mt][nt][r] = 0.0f;

    int ntiles = K >> 5;   // kt steps of 32
    for (int kt = 0; kt < ntiles; kt++) {
        bool more = (kt + 1 < ntiles);
        if (more) {
            #pragma unroll
            for (int i = 0; i < 4; i++) {
                pa[i] = *(const float4*)(Abase + (size_t)am[i] * K + (kt + 1) * 32 + ac[i]);
                pb[i] = *(const float4*)(Bbase + ((size_t)(kt + 1) * 32 + bk[i]) * N + bn[i]);
            }
        }
        #pragma unroll
        for (int k8 = 0; k8 < 4; k8++) {
            int kb = k8 * 8;
            uint32_t a[4][4], b[4][2];
            #pragma unroll
            for (int mt = 0; mt < 4; mt++) {
                int r = wm + mt * 16 + gr;
                a[mt][0] = As[r * AS_STRIDE + kb + gk];
                a[mt][1] = As[(r + 8) * AS_STRIDE + kb + gk];
                a[mt][2] = As[r * AS_STRIDE + kb + gk + 4];
                a[mt][3] = As[(r + 8) * AS_STRIDE + kb + gk + 4];
            }
            #pragma unroll
            for (int nt = 0; nt < 4; nt++) {
                int cn = wn + nt * 8 + gr;
                b[nt][0] = Bs[(kb + gk) * BS_STRIDE + cn];
                b[nt][1] = Bs[(kb + gk + 4) * BS_STRIDE + cn];
            }
            #pragma unroll
            for (int mt = 0; mt < 4; mt++)
                #pragma unroll
                for (int nt = 0; nt < 4; nt++)
                    MMA_TF32(acc[mt][nt], a[mt], b[nt]);
        }
        __syncthreads();
        if (more) {
            #pragma unroll
            for (int i = 0; i < 4; i++) {
                uint4 ua = make_uint4(f2tf(pa[i].x), f2tf(pa[i].y), f2tf(pa[i].z), f2tf(pa[i].w));
                uint4 ub = make_uint4(f2tf(pb[i].x), f2tf(pb[i].y), f2tf(pb[i].z), f2tf(pb[i].w));
                *(uint4*)&As[am[i] * AS_STRIDE + ac[i]] = ua;
                *(uint4*)&Bs[bk[i] * BS_STRIDE + bn[i]] = ub;
            }
            __syncthreads();
        }
    }

    // ---------------- epilogue (C fragment: rows gr & gr+8, cols 2*gk, 2*gk+1) ----------------
    #pragma unroll
    for (int mt = 0; mt < 4; mt++) {
        int r0 = brow + wm + mt * 16 + gr;
        int r1 = r0 + 8;
        #pragma unroll
        for (int nt = 0; nt < 4; nt++) {
            int c = bcol + wn + nt * 8 + (gk << 1);
            float2 bv = *(const float2*)(bias + c);
            float2 lo = make_float2(acc[mt][nt][0] + bv.x, acc[mt][nt][1] + bv.y);
            float2 hi = make_float2(acc[mt][nt][2] + bv.x, acc[mt][nt][3] + bv.y);
            if (EPI == 1) {
                float2 rl = *(const float2*)(res + (size_t)r0 * N + c);
                float2 rh = *(const float2*)(res + (size_t)r1 * N + c);
                lo.x += rl.x; lo.y += rl.y; hi.x += rh.x; hi.y += rh.y;
            }
            if (EPI == 2) {
                lo.x = fmaxf(lo.x, 0.0f); lo.y = fmaxf(lo.y, 0.0f);
                hi.x = fmaxf(hi.x, 0.0f); hi.y = fmaxf(hi.y, 0.0f);
            }
            if (EPI == 0) {
                // scatter: (row = b*S+s, col = h*DK+dk) -> [((b*H+h)*S+s)*DK+dk]
                int h_ = c >> 6, dkc = c & 63;
                int b0_ = r0 >> 11, s0_ = r0 & 2047;
                int b1_ = r1 >> 11, s1_ = r1 & 2047;
                *(float2*)(C + ((((size_t)b0_ * HH + h_) * SS + s0_) << 6) + dkc) = lo;
                *(float2*)(C + ((((size_t)b1_ * HH + h_) * SS + s1_) << 6) + dkc) = hi;
            } else {
                *(float2*)(C + (size_t)r0 * N + c) = lo;
                *(float2*)(C + (size_t)r1 * N + c) = hi;
            }
        }
    }
}

// ---------------- Flash attention, fp32, 64-row q tiles ----------------
__global__ __launch_bounds__(256)
void attn_kernel(const float* __restrict__ q, const float* __restrict__ k,
                 const float* __restrict__ v, const int* __restrict__ mask,
                 float* __restrict__ ctx) {
    __shared__ float Qs[64 * 64];
    __shared__ float KVs[64 * 64];
    __shared__ float Ps[64 * 64];

    int tid = threadIdx.x;
    int bh = blockIdx.y;
    int qt = blockIdx.x;
    int b = bh >> 4;
    const float* qbase = q + ((size_t)bh * SS + qt * 64) * DKK;
    const float* kbase = k + (size_t)bh * SS * DKK;
    const float* vbase = v + (size_t)bh * SS * DKK;

    #pragma unroll
    for (int i = 0; i < 4; i++) {
        int f = tid + i * 256;
        int r = f >> 4;
        int c = (f & 15) << 2;
        float4 t = *(const float4*)(qbase + r * 64 + c);
        t.x *= 0.125f; t.y *= 0.125f; t.z *= 0.125f; t.w *= 0.125f;
        *(float4*)(Qs + r * 64 + c) = t;
    }
    int ty = tid >> 4, tx = tid & 15;
    int ty4 = ty << 2, tx4 = tx << 2;

    float o[4][4];
    float mI[4], lI[4];
    #pragma unroll
    for (int i = 0; i < 4; i++) {
        mI[i] = -1e30f; lI[i] = 0.0f;
        #pragma unroll
        for (int j = 0; j < 4; j++) o[i][j] = 0.0f;
    }

    for (int kt = 0; kt < SS / 64; kt++) {
        __syncthreads();
        #pragma unroll
        for (int i = 0; i < 4; i++) {
            int f = tid + i * 256;
            int r = f >> 4;
            int c = (f & 15) << 2;
            float4 t = *(const float4*)(kbase + (size_t)(kt * 64 + r) * 64 + c);
            KVs[(c + 0) * 64 + r] = t.x;
            KVs[(c + 1) * 64 + r] = t.y;
            KVs[(c + 2) * 64 + r] = t.z;
            KVs[(c + 3) * 64 + r] = t.w;
        }
        __syncthreads();

        float s[4][4];
        #pragma unroll
        for (int i = 0; i < 4; i++)
            #pragma unroll
            for (int j = 0; j < 4; j++) s[i][j] = 0.0f;

        #pragma unroll 4
        for (int dk0 = 0; dk0 < 64; dk0 += 4) {
            float4 qv[4], kv4[4];
            #pragma unroll
            for (int i = 0; i < 4; i++) qv[i] = *(const float4*)(Qs + (ty4 + i) * 64 + dk0);
            #pragma unroll
            for (int u = 0; u < 4; u++) kv4[u] = *(const float4*)(KVs + (dk0 + u) * 64 + tx4);
            #pragma unroll
            for (int i = 0; i < 4; i++) {
                float qx = qv[i].x, qy = qv[i].y, qz = qv[i].z, qw = qv[i].w;
                s[i][0] += qx * kv4[0].x + qy * kv4[1].x + qz * kv4[2].x + qw * kv4[3].x;
                s[i][1] += qx * kv4[0].y + qy * kv4[1].y + qz * kv4[2].y + qw * kv4[3].y;
                s[i][2] += qx * kv4[0].z + qy * kv4[1].z + qz * kv4[2].z + qw * kv4[3].z;
                s[i][3] += qx * kv4[0].w + qy * kv4[1].w + qz * kv4[2].w + qw * kv4[3].w;
            }
        }

        int4 mv = *(const int4*)(mask + b * SS + kt * 64 + tx4);
        if (mv.x == 0) { s[0][0] = s[1][0] = s[2][0] = s[3][0] = -1e9f; }
        if (mv.y == 0) { s[0][1] = s[1][1] = s[2][1] = s[3][1] = -1e9f; }
        if (mv.z == 0) { s[0][2] = s[1][2] = s[2][2] = s[3][2] = -1e9f; }
        if (mv.w == 0) { s[0][3] = s[1][3] = s[2][3] = s[3][3] = -1e9f; }

        #pragma unroll
        for (int i = 0; i < 4; i++) {
            float rm = fmaxf(fmaxf(s[i][0], s[i][1]), fmaxf(s[i][2], s[i][3]));
            #pragma unroll
            for (int off = 1; off < 16; off <<= 1)
                rm = fmaxf(rm, __shfl_xor_sync(0xffffffffu, rm, off));
            float nm = fmaxf(mI[i], rm);
            float corr = __expf(mI[i] - nm);
            float rs = 0.0f;
            #pragma unroll
            for (int j = 0; j < 4; j++) { s[i][j] = __expf(s[i][j] - nm); rs += s[i][j]; }
            #pragma unroll
            for (int off = 1; off < 16; off <<= 1)
                rs += __shfl_xor_sync(0xffffffffu, rs, off);
            lI[i] = lI[i] * corr + rs;
            mI[i] = nm;
            #pragma unroll
            for (int j = 0; j < 4; j++) o[i][j] *= corr;
            *(float4*)(Ps + (ty4 + i) * 64 + tx4) = make_float4(s[i][0], s[i][1], s[i][2], s[i][3]);
        }
        __syncthreads();

        #pragma unroll
        for (int i = 0; i < 4; i++) {
            int f = tid + i * 256;
            int r = f >> 4;
            int c = (f & 15) << 2;
            *(float4*)(KVs + r * 64 + c) =
                *(const float4*)(vbase + (size_t)(kt * 64 + r) * 64 + c);
        }
        __syncthreads();

        #pragma unroll 4
        for (int kk = 0; kk < 64; kk += 4) {
            float4 pv[4], vv[4];
            #pragma unroll
            for (int i = 0; i < 4; i++) pv[i] = *(const float4*)(Ps + (ty4 + i) * 64 + kk);
            #pragma unroll
            for (int u = 0; u < 4; u++) vv[u] = *(const float4*)(KVs + (kk + u) * 64 + tx4);
            #pragma unroll
            for (int i = 0; i < 4; i++) {
                float px = pv[i].x, py = pv[i].y, pz = pv[i].z, pw = pv[i].w;
                o[i][0] += px * vv[0].x + py * vv[1].x + pz * vv[2].x + pw * vv[3].x;
                o[i][1] += px * vv[0].y + py * vv[1].y + pz * vv[2].y + pw * vv[3].y;
                o[i][2] += px * vv[0].z + py * vv[1].z + pz * vv[2].z + pw * vv[3].z;
                o[i][3] += px * vv[0].w + py * vv[1].w + pz * vv[2].w + pw * vv[3].w;
            }
        }
    }

    int h = bh & 15;
    #pragma unroll
    for (int i = 0; i < 4; i++) {
        float inv = 1.0f / lI[i];
        int srow = qt * 64 + ty4 + i;
        float4 r4 = make_float4(o[i][0] * inv, o[i][1] * inv, o[i][2] * inv, o[i][3] * inv);
        *(float4*)(ctx + ((size_t)(b * SS + srow)) * DD + h * 64 + tx4) = r4;
    }
}

// ---------------- launch ----------------
extern "C" void kernel_launch(void* const* d_in, const int* in_sizes, int n_in,
                              void* d_out, int out_size) {
    const float* x    = (const float*)d_in[0];
    const int*   mask = (const int*)  d_in[1];
    const float* Wq   = (const float*)d_in[2];
    const float* bq   = (const float*)d_in[3];
    const float* Wk   = (const float*)d_in[4];
    const float* bk   = (const float*)d_in[5];
    const float* Wv   = (const float*)d_in[6];
    const float* bv   = (const float*)d_in[7];
    const float* Wo   = (const float*)d_in[8];
    const float* bo   = (const float*)d_in[9];
    const float* W1   = (const float*)d_in[10];
    const float* b1   = (const float*)d_in[11];
    const float* W2   = (const float*)d_in[12];
    const float* b2   = (const float*)d_in[13];
    const float* a1   = (const float*)d_in[14];
    const float* be1  = (const float*)d_in[15];
    const float* a2   = (const float*)d_in[16];
    const float* be2  = (const float*)d_in[17];
    float* out = (float*)d_out;

    float *xn = nullptr, *q = nullptr, *k = nullptr, *v = nullptr;
    float *ctx = nullptr, *x1 = nullptr, *h = nullptr;
    cudaGetSymbolAddress((void**)&xn,  g_xn);
    cudaGetSymbolAddress((void**)&q,   g_q);
    cudaGetSymbolAddress((void**)&k,   g_k);
    cudaGetSymbolAddress((void**)&v,   g_v);
    cudaGetSymbolAddress((void**)&ctx, g_ctx);
    cudaGetSymbolAddress((void**)&x1,  g_x1);
    cudaGetSymbolAddress((void**)&h,   g_h);

    dim3 blk(256);
    dim3 g_dxd(DD / 128, NROW / 128);   // (8, 32)
    dim3 g_ffn1(DFF / 128, NROW / 128); // (32, 32)

    ln_kernel<<<NROW, blk>>>(x, a1, be1, xn);
    gemm_tc<0><<<g_dxd, blk>>>(xn, Wq, bq, nullptr, q, NROW, DD, DD);
    gemm_tc<0><<<g_dxd, blk>>>(xn, Wk, bk, nullptr, k, NROW, DD, DD);
    gemm_tc<0><<<g_dxd, blk>>>(xn, Wv, bv, nullptr, v, NROW, DD, DD);
    attn_kernel<<<dim3(SS / 64, BB * HH), blk>>>(q, k, v, mask, ctx);
    gemm_tc<1><<<g_dxd, blk>>>(ctx, Wo, bo, x, x1, NROW, DD, DD);
    ln_kernel<<<NROW, blk>>>(x1, a2, be2, xn);
    gemm_tc<2><<<g_ffn1, blk>>>(xn, W1, b1, nullptr, h, NROW, DFF, DD);
    gemm_tc<1><<<g_dxd, blk>>>(h, W2, b2, x1, out, NROW, DD, DFF);
}

// round 8
// speedup vs baseline: 2.7527x; 1.5773x over previous
#include <cuda_runtime.h>
#include <math.h>
#include <stdint.h>

// Problem dims
#define BB 2
#define SS 2048
#define DD 1024
#define HH 16
#define DKK 64
#define DFF 4096
#define NROW 4096   // B*S

// ---------------- scratch (device globals; no allocation allowed) ----------------
__device__ float g_xn [NROW * DD];
__device__ float g_q  [NROW * DD];
__device__ float g_k  [NROW * DD];
__device__ float g_v  [NROW * DD];
__device__ float g_ctx[NROW * DD];
__device__ float g_x1 [NROW * DD];
__device__ float g_h  [NROW * DFF];

// ---------------- LayerNorm (unbiased std, eps added to std) ----------------
__global__ __launch_bounds__(256)
void ln_kernel(const float* __restrict__ x, const float* __restrict__ alpha,
               const float* __restrict__ beta, float* __restrict__ y) {
    __shared__ float red[8];
    int row = blockIdx.x;
    int tid = threadIdx.x;
    const float* xr = x + (size_t)row * DD;
    float4 v = *(const float4*)(xr + tid * 4);
    float s = v.x + v.y + v.z + v.w;
    #pragma unroll
    for (int off = 16; off > 0; off >>= 1) s += __shfl_xor_sync(0xffffffffu, s, off);
    if ((tid & 31) == 0) red[tid >> 5] = s;
    __syncthreads();
    float tot = red[0] + red[1] + red[2] + red[3] + red[4] + red[5] + red[6] + red[7];
    float mean = tot * (1.0f / 1024.0f);
    float dx = v.x - mean, dy = v.y - mean, dz = v.z - mean, dw = v.w - mean;
    float sq = dx * dx + dy * dy + dz * dz + dw * dw;
    #pragma unroll
    for (int off = 16; off > 0; off >>= 1) sq += __shfl_xor_sync(0xffffffffu, sq, off);
    __syncthreads();
    if ((tid & 31) == 0) red[tid >> 5] = sq;
    __syncthreads();
    float var = (red[0] + red[1] + red[2] + red[3] + red[4] + red[5] + red[6] + red[7])
                * (1.0f / 1023.0f);            // ddof=1 (unbiased, torch default)
    float sc = alpha[0] / (sqrtf(var) + 1e-6f); // eps added to std, not var
    float be = beta[0];
    float4 o = make_float4(dx * sc + be, dy * sc + be, dz * sc + be, dw * sc + be);
    *(float4*)(y + (size_t)row * DD + tid * 4) = o;
}

// ---------------- TF32 helpers ----------------
__device__ __forceinline__ uint32_t f2tf(float f) {
    uint32_t u;
    asm("cvt.rna.tf32.f32 %0, %1;" : "=r"(u) : "f"(f));
    return u;
}

#define MMA_TF32(d, a, b) \
    asm volatile("mma.sync.aligned.m16n8k8.row.col.f32.tf32.tf32.f32 " \
                 "{%0,%1,%2,%3},{%4,%5,%6,%7},{%8,%9},{%0,%1,%2,%3};" \
                 : "+f"(d[0]), "+f"(d[1]), "+f"(d[2]), "+f"(d[3]) \
                 : "r"(a[0]), "r"(a[1]), "r"(a[2]), "r"(a[3]), "r"(b[0]), "r"(b[1]))

// ---------------- TF32 tensor-core GEMM body, 128x128 tile, kt=32 ----------------
// EPI: 0 = bias + scatter to [B,H,S,DK]; 1 = bias + residual add; 2 = bias + ReLU
#define AS_STRIDE 36    // frag-load bank = 4*(lane>>2)+(lane&3), conflict-free
#define BS_STRIDE 136   // frag-load bank = 8*(lane&3)+(lane>>2), conflict-free

template <int EPI>
__device__ __forceinline__
void gemm_body(const float* __restrict__ A, const float* __restrict__ Bm,
               const float* __restrict__ bias, const float* __restrict__ res,
               float* __restrict__ C, int N, int K, int brow, int bcol,
               uint32_t* As, uint32_t* Bs) {
    int tid  = threadIdx.x;
    int lane = tid & 31;
    int wid  = tid >> 5;

    int wm = (wid >> 2) * 64;   // warp m base: 0 / 64
    int wn = (wid & 3) * 32;    // warp n base: 0/32/64/96
    int gr = lane >> 2;         // 0..7
    int gk = lane & 3;          // 0..3

    int am[4], ac[4], bk[4], bn[4];
    #pragma unroll
    for (int i = 0; i < 4; i++) {
        int idx = tid + i * 256;
        am[i] = idx >> 3;  ac[i] = (idx & 7) << 2;    // A tile 128x32
        bk[i] = idx >> 5;  bn[i] = (idx & 31) << 2;   // B tile 32x128
    }
    const float* Abase = A + (size_t)brow * K;
    const float* Bbase = Bm + bcol;

    float4 pa[4], pb[4];
    #pragma unroll
    for (int i = 0; i < 4; i++) {
        pa[i] = *(const float4*)(Abase + (size_t)am[i] * K + ac[i]);
        pb[i] = *(const float4*)(Bbase + (size_t)bk[i] * N + bn[i]);
    }
    #pragma unroll
    for (int i = 0; i < 4; i++) {
        uint4 ua = make_uint4(f2tf(pa[i].x), f2tf(pa[i].y), f2tf(pa[i].z), f2tf(pa[i].w));
        uint4 ub = make_uint4(f2tf(pb[i].x), f2tf(pb[i].y), f2tf(pb[i].z), f2tf(pb[i].w));
        *(uint4*)&As[am[i] * AS_STRIDE + ac[i]] = ua;
        *(uint4*)&Bs[bk[i] * BS_STRIDE + bn[i]] = ub;
    }
    __syncthreads();

    float acc[4][4][4];
    #pragma unroll
    for (int mt = 0; mt < 4; mt++)
        #pragma unroll
        for (int nt = 0; nt < 4; nt++)
            #pragma unroll
            for (int r = 0; r < 4; r++) acc[mt][nt][r] = 0.0f;

    int ntiles = K >> 5;
    for (int kt = 0; kt < ntiles; kt++) {
        bool more = (kt + 1 < ntiles);
        if (more) {
            #pragma unroll
            for (int i = 0; i < 4; i++) {
                pa[i] = *(const float4*)(Abase + (size_t)am[i] * K + (kt + 1) * 32 + ac[i]);
                pb[i] = *(const float4*)(Bbase + ((size_t)(kt + 1) * 32 + bk[i]) * N + bn[i]);
            }
        }
        #pragma unroll
        for (int k8 = 0; k8 < 4; k8++) {
            int kb = k8 * 8;
            uint32_t a[4][4], b[4][2];
            #pragma unroll
            for (int mt = 0; mt < 4; mt++) {
                int r = wm + mt * 16 + gr;
                a[mt][0] = As[r * AS_STRIDE + kb + gk];
                a[mt][1] = As[(r + 8) * AS_STRIDE + kb + gk];
                a[mt][2] = As[r * AS_STRIDE + kb + gk + 4];
                a[mt][3] = As[(r + 8) * AS_STRIDE + kb + gk + 4];
            }
            #pragma unroll
            for (int nt = 0; nt < 4; nt++) {
                int cn = wn + nt * 8 + gr;
                b[nt][0] = Bs[(kb + gk) * BS_STRIDE + cn];
                b[nt][1] = Bs[(kb + gk + 4) * BS_STRIDE + cn];
            }
            #pragma unroll
            for (int mt = 0; mt < 4; mt++)
                #pragma unroll
                for (int nt = 0; nt < 4; nt++)
                    MMA_TF32(acc[mt][nt], a[mt], b[nt]);
        }
        __syncthreads();
        if (more) {
            #pragma unroll
            for (int i = 0; i < 4; i++) {
                uint4 ua = make_uint4(f2tf(pa[i].x), f2tf(pa[i].y), f2tf(pa[i].z), f2tf(pa[i].w));
                uint4 ub = make_uint4(f2tf(pb[i].x), f2tf(pb[i].y), f2tf(pb[i].z), f2tf(pb[i].w));
                *(uint4*)&As[am[i] * AS_STRIDE + ac[i]] = ua;
                *(uint4*)&Bs[bk[i] * BS_STRIDE + bn[i]] = ub;
            }
            __syncthreads();
        }
    }

    #pragma unroll
    for (int mt = 0; mt < 4; mt++) {
        int r0 = brow + wm + mt * 16 + gr;
        int r1 = r0 + 8;
        #pragma unroll
        for (int nt = 0; nt < 4; nt++) {
            int c = bcol + wn + nt * 8 + (gk << 1);
            float2 bv = *(const float2*)(bias + c);
            float2 lo = make_float2(acc[mt][nt][0] + bv.x, acc[mt][nt][1] + bv.y);
            float2 hi = make_float2(acc[mt][nt][2] + bv.x, acc[mt][nt][3] + bv.y);
            if (EPI == 1) {
                float2 rl = *(const float2*)(res + (size_t)r0 * N + c);
                float2 rh = *(const float2*)(res + (size_t)r1 * N + c);
                lo.x += rl.x; lo.y += rl.y; hi.x += rh.x; hi.y += rh.y;
            }
            if (EPI == 2) {
                lo.x = fmaxf(lo.x, 0.0f); lo.y = fmaxf(lo.y, 0.0f);
                hi.x = fmaxf(hi.x, 0.0f); hi.y = fmaxf(hi.y, 0.0f);
            }
            if (EPI == 0) {
                int h_ = c >> 6, dkc = c & 63;
                int b0_ = r0 >> 11, s0_ = r0 & 2047;
                int b1_ = r1 >> 11, s1_ = r1 & 2047;
                *(float2*)(C + ((((size_t)b0_ * HH + h_) * SS + s0_) << 6) + dkc) = lo;
                *(float2*)(C + ((((size_t)b1_ * HH + h_) * SS + s1_) << 6) + dkc) = hi;
            } else {
                *(float2*)(C + (size_t)r0 * N + c) = lo;
                *(float2*)(C + (size_t)r1 * N + c) = hi;
            }
        }
    }
}

template <int EPI>
__global__ __launch_bounds__(256)
void gemm_tc(const float* __restrict__ A, const float* __restrict__ Bm,
             const float* __restrict__ bias, const float* __restrict__ res,
             float* __restrict__ C, int N, int K) {
    __shared__ uint32_t As[128 * AS_STRIDE];
    __shared__ uint32_t Bs[32 * BS_STRIDE];
    gemm_body<EPI>(A, Bm, bias, res, C, N, K, blockIdx.y * 128, blockIdx.x * 128, As, Bs);
}

// fused QKV: gridDim.z selects weight/bias/output
__global__ __launch_bounds__(256)
void gemm_qkv(const float* __restrict__ A,
              const float* __restrict__ W0, const float* __restrict__ W1q, const float* __restrict__ W2q,
              const float* __restrict__ c0, const float* __restrict__ c1, const float* __restrict__ c2,
              float* __restrict__ O0, float* __restrict__ O1, float* __restrict__ O2) {
    __shared__ uint32_t As[128 * AS_STRIDE];
    __shared__ uint32_t Bs[32 * BS_STRIDE];
    int z = blockIdx.z;
    const float* W = (z == 0) ? W0 : (z == 1) ? W1q : W2q;
    const float* bb = (z == 0) ? c0 : (z == 1) ? c1 : c2;
    float* O = (z == 0) ? O0 : (z == 1) ? O1 : O2;
    gemm_body<0>(A, W, bb, nullptr, O, DD, DD, blockIdx.y * 128, blockIdx.x * 128, As, Bs);
}

// ---------------- TF32 tensor-core flash attention ----------------
// grid (S/64, B*H), 128 threads (4 warps), each warp m16 x n64 of a 64x64 tile.
#define ATT_ST 68   // 64 + 4 pad: fragment LDS bank = lane -> conflict-free

__global__ __launch_bounds__(128)
void attn_tc(const float* __restrict__ q, const float* __restrict__ k,
             const float* __restrict__ v, const int* __restrict__ mask,
             float* __restrict__ ctx) {
    __shared__ uint32_t KVs[64 * ATT_ST];  // K natural [kv][dk], then V transposed [dk][kv]
    __shared__ uint32_t Ps[64 * ATT_ST];   // P tf32 [qrow][kv]

    int tid  = threadIdx.x;
    int lane = tid & 31;
    int wid  = tid >> 5;     // 0..3
    int gr   = lane >> 2;    // 0..7
    int gk   = lane & 3;     // 0..3
    int wm   = wid * 16;

    int bh = blockIdx.y;
    int qt = blockIdx.x;
    int b  = bh >> 4;
    const float* qbase = q + ((size_t)bh * SS + qt * 64) * DKK;
    const float* kbase = k + (size_t)bh * SS * DKK;
    const float* vbase = v + (size_t)bh * SS * DKK;
    const int*   mbase = mask + b * SS;

    // Q fragments in registers (scaled by 1/sqrt(DK)), 8 k-steps x 4 regs
    uint32_t qf[8][4];
    #pragma unroll
    for (int ks = 0; ks < 8; ks++) {
        int kc = ks * 8 + gk;
        qf[ks][0] = f2tf(0.125f * qbase[(wm + gr) * 64 + kc]);
        qf[ks][1] = f2tf(0.125f * qbase[(wm + gr + 8) * 64 + kc]);
        qf[ks][2] = f2tf(0.125f * qbase[(wm + gr) * 64 + kc + 4]);
        qf[ks][3] = f2tf(0.125f * qbase[(wm + gr + 8) * 64 + kc + 4]);
    }

    float o[8][4];
    #pragma unroll
    for (int nt = 0; nt < 8; nt++)
        #pragma unroll
        for (int r = 0; r < 4; r++) o[nt][r] = 0.0f;
    float m_lo = -1e30f, m_hi = -1e30f, l_lo = 0.0f, l_hi = 0.0f;

    for (int kt = 0; kt < SS / 64; kt++) {
        __syncthreads();   // prev PV reads done before KVs overwrite
        // K tile natural [kv][dk]
        #pragma unroll
        for (int i = 0; i < 8; i++) {
            int f = tid + i * 128;
            int r = f >> 4;
            int c = (f & 15) << 2;
            float4 t = *(const float4*)(kbase + (size_t)(kt * 64 + r) * 64 + c);
            uint4 u = make_uint4(f2tf(t.x), f2tf(t.y), f2tf(t.z), f2tf(t.w));
            *(uint4*)&KVs[r * ATT_ST + c] = u;
        }
        __syncthreads();

        // S = Q K^T  (K natural layout == col-major B fragment)
        float s[8][4];
        #pragma unroll
        for (int nt = 0; nt < 8; nt++)
            #pragma unroll
            for (int r = 0; r < 4; r++) s[nt][r] = 0.0f;
        #pragma unroll
        for (int ks = 0; ks < 8; ks++) {
            int kb = ks * 8;
            #pragma unroll
            for (int nt = 0; nt < 8; nt++) {
                uint32_t bfr[2];
                bfr[0] = KVs[(nt * 8 + gr) * ATT_ST + kb + gk];
                bfr[1] = KVs[(nt * 8 + gr) * ATT_ST + kb + gk + 4];
                MMA_TF32(s[nt], qf[ks], bfr);
            }
        }

        // mask + row max
        float rmax_lo = -1e30f, rmax_hi = -1e30f;
        #pragma unroll
        for (int nt = 0; nt < 8; nt++) {
            int2 mv = *(const int2*)(mbase + kt * 64 + nt * 8 + (gk << 1));
            if (mv.x == 0) { s[nt][0] = -1e9f; s[nt][2] = -1e9f; }
            if (mv.y == 0) { s[nt][1] = -1e9f; s[nt][3] = -1e9f; }
            rmax_lo = fmaxf(rmax_lo, fmaxf(s[nt][0], s[nt][1]));
            rmax_hi = fmaxf(rmax_hi, fmaxf(s[nt][2], s[nt][3]));
        }
        rmax_lo = fmaxf(rmax_lo, __shfl_xor_sync(0xffffffffu, rmax_lo, 1));
        rmax_lo = fmaxf(rmax_lo, __shfl_xor_sync(0xffffffffu, rmax_lo, 2));
        rmax_hi = fmaxf(rmax_hi, __shfl_xor_sync(0xffffffffu, rmax_hi, 1));
        rmax_hi = fmaxf(rmax_hi, __shfl_xor_sync(0xffffffffu, rmax_hi, 2));

        float nm_lo = fmaxf(m_lo, rmax_lo);
        float nm_hi = fmaxf(m_hi, rmax_hi);
        float corr_lo = __expf(m_lo - nm_lo);
        float corr_hi = __expf(m_hi - nm_hi);
        float rs_lo = 0.0f, rs_hi = 0.0f;
        #pragma unroll
        for (int nt = 0; nt < 8; nt++) {
            s[nt][0] = __expf(s[nt][0] - nm_lo);
            s[nt][1] = __expf(s[nt][1] - nm_lo);
            s[nt][2] = __expf(s[nt][2] - nm_hi);
            s[nt][3] = __expf(s[nt][3] - nm_hi);
            rs_lo += s[nt][0] + s[nt][1];
            rs_hi += s[nt][2] + s[nt][3];
        }
        rs_lo += __shfl_xor_sync(0xffffffffu, rs_lo, 1);
        rs_lo += __shfl_xor_sync(0xffffffffu, rs_lo, 2);
        rs_hi += __shfl_xor_sync(0xffffffffu, rs_hi, 1);
        rs_hi += __shfl_xor_sync(0xffffffffu, rs_hi, 2);
        l_lo = l_lo * corr_lo + rs_lo;  m_lo = nm_lo;
        l_hi = l_hi * corr_hi + rs_hi;  m_hi = nm_hi;
        #pragma unroll
        for (int nt = 0; nt < 8; nt++) {
            o[nt][0] *= corr_lo; o[nt][1] *= corr_lo;
            o[nt][2] *= corr_hi; o[nt][3] *= corr_hi;
        }

        // P -> smem (tf32)
        #pragma unroll
        for (int nt = 0; nt < 8; nt++) {
            int c = nt * 8 + (gk << 1);
            *(uint2*)&Ps[(wm + gr) * ATT_ST + c]     = make_uint2(f2tf(s[nt][0]), f2tf(s[nt][1]));
            *(uint2*)&Ps[(wm + gr + 8) * ATT_ST + c] = make_uint2(f2tf(s[nt][2]), f2tf(s[nt][3]));
        }
        __syncthreads();   // P written; K reads done

        // V transposed [dk][kv]
        #pragma unroll
        for (int i = 0; i < 8; i++) {
            int f = tid + i * 128;
            int r = f >> 4;
            int c = (f & 15) << 2;
            float4 t = *(const float4*)(vbase + (size_t)(kt * 64 + r) * 64 + c);
            KVs[(c + 0) * ATT_ST + r] = f2tf(t.x);
            KVs[(c + 1) * ATT_ST + r] = f2tf(t.y);
            KVs[(c + 2) * ATT_ST + r] = f2tf(t.z);
            KVs[(c + 3) * ATT_ST + r] = f2tf(t.w);
        }
        __syncthreads();

        // O += P V   (A = P row-major, B = V^T col-major-of-[kv] = Vs[dk][kv])
        #pragma unroll
        for (int ks = 0; ks < 8; ks++) {
            int kb = ks * 8;
            uint32_t af[4];
            af[0] = Ps[(wm + gr) * ATT_ST + kb + gk];
            af[1] = Ps[(wm + gr + 8) * ATT_ST + kb + gk];
            af[2] = Ps[(wm + gr) * ATT_ST + kb + gk + 4];
            af[3] = Ps[(wm + gr + 8) * ATT_ST + kb + gk + 4];
            #pragma unroll
            for (int nt = 0; nt < 8; nt++) {
                uint32_t bfr[2];
                bfr[0] = KVs[(nt * 8 + gr) * ATT_ST + kb + gk];
                bfr[1] = KVs[(nt * 8 + gr) * ATT_ST + kb + gk + 4];
                MMA_TF32(o[nt], af, bfr);
            }
        }
    }

    // epilogue: divide by l, write ctx[B,S,D] at col h*64+dk
    int h = bh & 15;
    float inv_lo = 1.0f / l_lo;
    float inv_hi = 1.0f / l_hi;
    size_t rbase = (size_t)(b * SS + qt * 64);
    #pragma unroll
    for (int nt = 0; nt < 8; nt++) {
        int c = h * 64 + nt * 8 + (gk << 1);
        *(float2*)(ctx + (rbase + wm + gr) * DD + c) =
            make_float2(o[nt][0] * inv_lo, o[nt][1] * inv_lo);
        *(float2*)(ctx + (rbase + wm + gr + 8) * DD + c) =
            make_float2(o[nt][2] * inv_hi, o[nt][3] * inv_hi);
    }
}

// ---------------- launch ----------------
extern "C" void kernel_launch(void* const* d_in, const int* in_sizes, int n_in,
                              void* d_out, int out_size) {
    const float* x    = (const float*)d_in[0];
    const int*   mask = (const int*)  d_in[1];
    const float* Wq   = (const float*)d_in[2];
    const float* bq   = (const float*)d_in[3];
    const float* Wk   = (const float*)d_in[4];
    const float* bk   = (const float*)d_in[5];
    const float* Wv   = (const float*)d_in[6];
    const float* bv   = (const float*)d_in[7];
    const float* Wo   = (const float*)d_in[8];
    const float* bo   = (const float*)d_in[9];
    const float* W1   = (const float*)d_in[10];
    const float* b1   = (const float*)d_in[11];
    const float* W2   = (const float*)d_in[12];
    const float* b2   = (const float*)d_in[13];
    const float* a1   = (const float*)d_in[14];
    const float* be1  = (const float*)d_in[15];
    const float* a2   = (const float*)d_in[16];
    const float* be2  = (const float*)d_in[17];
    float* out = (float*)d_out;

    float *xn = nullptr, *q = nullptr, *k = nullptr, *v = nullptr;
    float *ctx = nullptr, *x1 = nullptr, *h = nullptr;
    cudaGetSymbolAddress((void**)&xn,  g_xn);
    cudaGetSymbolAddress((void**)&q,   g_q);
    cudaGetSymbolAddress((void**)&k,   g_k);
    cudaGetSymbolAddress((void**)&v,   g_v);
    cudaGetSymbolAddress((void**)&ctx, g_ctx);
    cudaGetSymbolAddress((void**)&x1,  g_x1);
    cudaGetSymbolAddress((void**)&h,   g_h);

    dim3 blk(256);
    dim3 g_qkv(DD / 128, NROW / 128, 3);  // (8, 32, 3) fused QKV
    dim3 g_dxd(DD / 128, NROW / 128);     // (8, 32)
    dim3 g_ffn1(DFF / 128, NROW / 128);   // (32, 32)

    ln_kernel<<<NROW, blk>>>(x, a1, be1, xn);
    gemm_qkv<<<g_qkv, blk>>>(xn, Wq, Wk, Wv, bq, bk, bv, q, k, v);
    attn_tc<<<dim3(SS / 64, BB * HH), 128>>>(q, k, v, mask, ctx);
    gemm_tc<1><<<g_dxd, blk>>>(ctx, Wo, bo, x, x1, DD, DD);
    ln_kernel<<<NROW, blk>>>(x1, a2, be2, xn);
    gemm_tc<2><<<g_ffn1, blk>>>(xn, W1, b1, nullptr, h, DFF, DD);
    gemm_tc<1><<<g_dxd, blk>>>(h, W2, b2, x1, out, DD, DFF);
}